// round 7
// baseline (speedup 1.0000x reference)
#include <cuda_runtime.h>
#include <math.h>
#include <stdint.h>

#define B_  4
#define S_  2048
#define D_  512
#define H_  8
#define HD_ 64
#define NR  (B_ * S_)   // 8192 rows

// Scratch buffers (no allocation allowed in kernel_launch).
__device__ __align__(16) float g_fused[NR * D_];
__device__ __align__(16) float g_Q[NR * D_];
__device__ __align__(16) float g_K[NR * D_];
__device__ __align__(16) float g_V[NR * D_];
__device__ __align__(16) float g_att[NR * D_];

// ---------------------------------------------------------------------------
// TF32 helpers
// ---------------------------------------------------------------------------
__device__ __forceinline__ uint32_t f2tf(float x) {
    uint32_t u;
    asm("cvt.rna.tf32.f32 %0, %1;" : "=r"(u) : "f"(x));
    return u;
}
__device__ __forceinline__ float f2tff(float x) {
    return __uint_as_float(f2tf(x));
}
// D(16x8,f32) += A(16x8,tf32,row) * B(8x8,tf32,col)
__device__ __forceinline__ void mma8(float* d, const uint32_t* a, const uint32_t* b) {
    asm volatile(
        "mma.sync.aligned.m16n8k8.row.col.f32.tf32.tf32.f32 "
        "{%0,%1,%2,%3}, {%4,%5,%6,%7}, {%8,%9}, {%0,%1,%2,%3};"
        : "+f"(d[0]), "+f"(d[1]), "+f"(d[2]), "+f"(d[3])
        : "r"(a[0]), "r"(a[1]), "r"(a[2]), "r"(a[3]), "r"(b[0]), "r"(b[1]));
}

// ---------------------------------------------------------------------------
// TF32 tensor-core GEMM: C[M,512] = A[M,K] @ Bw[K,512] + bias.
// Double-buffered smem: one __syncthreads per k-iter, LDG prefetch overlaps mma.
// Concat support: logical A row = A[0..KA) ++ A2[0..K-KA). 16-col k-tiles
// never straddle KA (512 | 16).
// CTA 128x128, 256 threads, 8 warps (2m x 4n), warp tile 64x32.
// ---------------------------------------------------------------------------
__global__ __launch_bounds__(256, 2) void gemm_tf32(
    const float* __restrict__ A, const float* __restrict__ A2, int KA,
    const float* __restrict__ Bw, const float* __restrict__ bias,
    float* __restrict__ C, int K)
{
    __shared__ float As[2][128][20];   // [m][k], pad: frag LDS conflict-free
    __shared__ float Bs[2][16][132];   // [k][n]

    const int tid  = threadIdx.x;
    const int lane = tid & 31, wid = tid >> 5;
    const int g = lane >> 2, t = lane & 3;
    const int wm = (wid >> 2) * 64;
    const int wn = (wid & 3) * 32;
    const int row0 = blockIdx.y * 128;
    const int col0 = blockIdx.x * 128;

    const int ar = tid >> 1;            // 0..127
    const int ac = (tid & 1) * 8;       // 0 or 8
    const int bk = tid >> 4;            // 0..15
    const int bc = (tid & 15) * 8;      // 0..120

    float acc[4][4][4];
    #pragma unroll
    for (int i = 0; i < 4; i++)
        #pragma unroll
        for (int j = 0; j < 4; j++)
            #pragma unroll
            for (int v = 0; v < 4; v++) acc[i][j][v] = 0.0f;

    const int niter = K >> 4;
    float4 pa0, pa1, pb0, pb1;

    auto prefetch = [&](int it) {
        int k0 = it << 4;
        const float* src = (k0 < KA) ? A : A2;
        int koff = (k0 < KA) ? k0 : k0 - KA;
        const float* p = &src[(size_t)(row0 + ar) * KA + koff + ac];
        pa0 = *(const float4*)p; pa1 = *(const float4*)(p + 4);
        const float* q = &Bw[(size_t)(k0 + bk) * D_ + col0 + bc];
        pb0 = *(const float4*)q; pb1 = *(const float4*)(q + 4);
    };
    auto stage = [&](int buf) {
        *(float4*)&As[buf][ar][ac]     = make_float4(f2tff(pa0.x), f2tff(pa0.y), f2tff(pa0.z), f2tff(pa0.w));
        *(float4*)&As[buf][ar][ac + 4] = make_float4(f2tff(pa1.x), f2tff(pa1.y), f2tff(pa1.z), f2tff(pa1.w));
        *(float4*)&Bs[buf][bk][bc]     = make_float4(f2tff(pb0.x), f2tff(pb0.y), f2tff(pb0.z), f2tff(pb0.w));
        *(float4*)&Bs[buf][bk][bc + 4] = make_float4(f2tff(pb1.x), f2tff(pb1.y), f2tff(pb1.z), f2tff(pb1.w));
    };

    prefetch(0);
    stage(0);
    __syncthreads();

    for (int it = 0; it < niter; it++) {
        const int cur = it & 1;
        if (it + 1 < niter) prefetch(it + 1);

        const uint32_t* Au = (const uint32_t*)As[cur];
        const uint32_t* Bu = (const uint32_t*)Bs[cur];
        #pragma unroll
        for (int ks = 0; ks < 2; ks++) {
            const int kk = ks * 8;
            uint32_t a[4][4];
            #pragma unroll
            for (int mt = 0; mt < 4; mt++) {
                int m = wm + mt * 16;
                a[mt][0] = Au[(m + g) * 20 + kk + t];
                a[mt][1] = Au[(m + g + 8) * 20 + kk + t];
                a[mt][2] = Au[(m + g) * 20 + kk + t + 4];
                a[mt][3] = Au[(m + g + 8) * 20 + kk + t + 4];
            }
            #pragma unroll
            for (int nt = 0; nt < 4; nt++) {
                int n = wn + nt * 8 + g;
                uint32_t bf[2] = { Bu[(kk + t) * 132 + n], Bu[(kk + t + 4) * 132 + n] };
                #pragma unroll
                for (int mt = 0; mt < 4; mt++) mma8(acc[mt][nt], a[mt], bf);
            }
        }

        if (it + 1 < niter) {
            stage(cur ^ 1);
            __syncthreads();
        }
    }

    // epilogue: bias + store (c0,c1 adjacent cols -> float2)
    #pragma unroll
    for (int mt = 0; mt < 4; mt++) {
        int r = row0 + wm + mt * 16 + g;
        #pragma unroll
        for (int nt = 0; nt < 4; nt++) {
            int c = col0 + wn + nt * 8 + 2 * t;
            float b0v = bias[c], b1v = bias[c + 1];
            *(float2*)&C[(size_t)r * D_ + c] =
                make_float2(acc[mt][nt][0] + b0v, acc[mt][nt][1] + b1v);
            *(float2*)&C[(size_t)(r + 8) * D_ + c] =
                make_float2(acc[mt][nt][2] + b0v, acc[mt][nt][3] + b1v);
        }
    }
}

// ---------------------------------------------------------------------------
// TF32 fused masked-softmax attention (flash-style).
//   sL[q,k] = (scale*log2e) * M[q,k] * (Q[q]·K[k])
//   p = exp2(sL - mL);  Zs = sum p;  pm = p*M;  Zm = sum pm
//   out[q] = (sum_k pm * V[k]) / (Zm + EPS*Zs)
// CTA: 128 q rows, 256 threads (8 warps x 16q). 32 key blocks of 64.
// Q fragments live in registers (loop-invariant). P scratch aliases the dead
// Q smem region (warp w's P rows == warp w's Q rows; mma.sync convergence
// orders the one-time Q-fragment loads before the first P store). K/V tiles
// are double-buffered: next tile LDG'd to regs during compute, STS'd after.
// M is read directly from gmem (L2-resident) in the C-fragment pattern.
// ---------------------------------------------------------------------------
#define AT_STRIDE 68
#define ATTN_SMEM ((128 * AT_STRIDE + 4 * 64 * AT_STRIDE) * 4)   // 104448 B

__global__ __launch_bounds__(256) void attn_tf32(
    const float* __restrict__ Qg, const float* __restrict__ Kg,
    const float* __restrict__ Vg, const float* __restrict__ Mg,
    float* __restrict__ Og)
{
    extern __shared__ float sm[];
    float* Qs = sm;                            // [128][68] (q x d) -> later P scratch
    float* Ks = sm + 128 * AT_STRIDE;          // [2][64][68] (k x d), tf32
    float* Vs = Ks + 2 * 64 * AT_STRIDE;       // [2][64][68] (k x d), tf32
    float* Ps = sm;                            // aliases Qs (per-warp 16 rows)

    const int tid  = threadIdx.x;
    const int lane = tid & 31, w = tid >> 5;
    const int g = lane >> 2, t = lane & 3;
    const int qw = w * 16;
    const int b = blockIdx.z, h = blockIdx.y, qb = blockIdx.x;

    const float CL = 0.125f * 1.4426950408889634f;   // scale * log2e

    const float* Qbase = Qg + ((size_t)(b * S_ + qb * 128)) * D_ + h * HD_;
    const float* Kbase = Kg + ((size_t)(b * S_)) * D_ + h * HD_;
    const float* Vbase = Vg + ((size_t)(b * S_)) * D_ + h * HD_;
    const float* Mrow0 = Mg + (size_t)b * S_ * S_ + (size_t)(qb * 128 + qw + g) * S_;
    const float* Mrow1 = Mrow0 + (size_t)8 * S_;
    float*       Obase = Og + ((size_t)(b * S_ + qb * 128)) * D_ + h * HD_;

    // ---- prologue: stage Q (tf32) and K/V tile 0 into smem ----
    #pragma unroll
    for (int itl = 0; itl < 8; itl++) {
        int idx = itl * 256 + tid;                 // 0..2047
        int r = idx >> 4, c = (idx & 15) * 4;
        float4 v = *(const float4*)&Qbase[(size_t)r * D_ + c];
        *(float4*)&Qs[r * AT_STRIDE + c] =
            make_float4(f2tff(v.x), f2tff(v.y), f2tff(v.z), f2tff(v.w));
    }
    #pragma unroll
    for (int itl = 0; itl < 4; itl++) {
        int idx = itl * 256 + tid;                 // 0..1023
        int r = idx >> 4, c = (idx & 15) * 4;
        float4 kv = *(const float4*)&Kbase[(size_t)r * D_ + c];
        float4 vv = *(const float4*)&Vbase[(size_t)r * D_ + c];
        *(float4*)&Ks[r * AT_STRIDE + c] =
            make_float4(f2tff(kv.x), f2tff(kv.y), f2tff(kv.z), f2tff(kv.w));
        *(float4*)&Vs[r * AT_STRIDE + c] =
            make_float4(f2tff(vv.x), f2tff(vv.y), f2tff(vv.z), f2tff(vv.w));
    }
    __syncthreads();

    // ---- Q fragments -> registers (loop-invariant) ----
    uint32_t qa[8][4];
    {
        const uint32_t* Qu = (const uint32_t*)Qs;
        #pragma unroll
        for (int ks = 0; ks < 8; ks++) {
            qa[ks][0] = Qu[(qw + g) * AT_STRIDE + ks * 8 + t];
            qa[ks][1] = Qu[(qw + g + 8) * AT_STRIDE + ks * 8 + t];
            qa[ks][2] = Qu[(qw + g) * AT_STRIDE + ks * 8 + t + 4];
            qa[ks][3] = Qu[(qw + g + 8) * AT_STRIDE + ks * 8 + t + 4];
        }
    }

    float acc[8][4];
    #pragma unroll
    for (int i = 0; i < 8; i++)
        #pragma unroll
        for (int v = 0; v < 4; v++) acc[i][v] = 0.0f;
    float mL0 = -1e30f, mL1 = -1e30f;
    float Zs0 = 0.f, Zs1 = 0.f, Zm0 = 0.f, Zm1 = 0.f;

    const int ldr = tid >> 4;              // cooperative-load row (0..15 base)
    const int ldc = (tid & 15) * 4;        // cooperative-load col

    for (int kb = 0; kb < S_ / 64; kb++) {
        const int cur = kb & 1;
        const bool has_next = (kb + 1 < S_ / 64);
        const float* Kscur = Ks + cur * 64 * AT_STRIDE;
        const float* Vscur = Vs + cur * 64 * AT_STRIDE;

        // prefetch next K tile into registers (consumed at end of iter)
        float4 kreg[4];
        if (has_next) {
            #pragma unroll
            for (int itl = 0; itl < 4; itl++) {
                int r = ldr + itl * 16;
                kreg[itl] = *(const float4*)&Kbase[(size_t)((kb + 1) * 64 + r) * D_ + ldc];
            }
        }

        // --- scores: S[16q,64k] = Q @ K^T (warp) ---
        const uint32_t* Ku = (const uint32_t*)Kscur;
        float sc[8][4];
        #pragma unroll
        for (int nt = 0; nt < 8; nt++)
            #pragma unroll
            for (int v = 0; v < 4; v++) sc[nt][v] = 0.0f;

        #pragma unroll
        for (int ks = 0; ks < 8; ks++) {
            #pragma unroll
            for (int nt = 0; nt < 8; nt++) {
                uint32_t bf[2] = { Ku[(nt * 8 + g) * AT_STRIDE + ks * 8 + t],
                                   Ku[(nt * 8 + g) * AT_STRIDE + ks * 8 + t + 4] };
                mma8(sc[nt], qa[ks], bf);
            }
        }

        // prefetch next V tile (sc regs of score phase now carry live data,
        // but these 16 regs overlap the softmax/PV window)
        float4 vreg[4];
        if (has_next) {
            #pragma unroll
            for (int itl = 0; itl < 4; itl++) {
                int r = ldr + itl * 16;
                vreg[itl] = *(const float4*)&Vbase[(size_t)((kb + 1) * 64 + r) * D_ + ldc];
            }
        }

        // --- mask * scale (log2 domain) from gmem, row max ---
        const float* Mc0 = Mrow0 + kb * 64;
        const float* Mc1 = Mrow1 + kb * 64;
        float mx0 = -1e30f, mx1 = -1e30f;
        #pragma unroll
        for (int nt = 0; nt < 8; nt++) {
            float2 mA = *(const float2*)&Mc0[nt * 8 + 2 * t];
            float2 mB = *(const float2*)&Mc1[nt * 8 + 2 * t];
            sc[nt][0] *= CL * mA.x;
            sc[nt][1] *= CL * mA.y;
            sc[nt][2] *= CL * mB.x;
            sc[nt][3] *= CL * mB.y;
            mx0 = fmaxf(mx0, fmaxf(sc[nt][0], sc[nt][1]));
            mx1 = fmaxf(mx1, fmaxf(sc[nt][2], sc[nt][3]));
        }
        mx0 = fmaxf(mx0, __shfl_xor_sync(0xffffffffu, mx0, 1));
        mx0 = fmaxf(mx0, __shfl_xor_sync(0xffffffffu, mx0, 2));
        mx1 = fmaxf(mx1, __shfl_xor_sync(0xffffffffu, mx1, 1));
        mx1 = fmaxf(mx1, __shfl_xor_sync(0xffffffffu, mx1, 2));

        float nm0 = fmaxf(mL0, mx0), nm1 = fmaxf(mL1, mx1);
        float corr0 = exp2f(mL0 - nm0), corr1 = exp2f(mL1 - nm1);
        mL0 = nm0; mL1 = nm1;

        // --- exp, Z accumulation, P (= p*M) to warp-private smem as tf32 ---
        float ls0 = 0.f, ls1 = 0.f, lm0 = 0.f, lm1 = 0.f;
        float* Pw = Ps + w * 16 * AT_STRIDE;
        #pragma unroll
        for (int nt = 0; nt < 8; nt++) {
            float2 mA = *(const float2*)&Mc0[nt * 8 + 2 * t];   // L1 hit
            float2 mB = *(const float2*)&Mc1[nt * 8 + 2 * t];
            float p0 = exp2f(sc[nt][0] - mL0);
            float p1 = exp2f(sc[nt][1] - mL0);
            float p2 = exp2f(sc[nt][2] - mL1);
            float p3 = exp2f(sc[nt][3] - mL1);
            ls0 += p0 + p1; ls1 += p2 + p3;
            p0 *= mA.x; p1 *= mA.y; p2 *= mB.x; p3 *= mB.y;
            lm0 += p0 + p1; lm1 += p2 + p3;
            *(float2*)&Pw[g * AT_STRIDE + nt * 8 + 2 * t] =
                make_float2(f2tff(p0), f2tff(p1));
            *(float2*)&Pw[(g + 8) * AT_STRIDE + nt * 8 + 2 * t] =
                make_float2(f2tff(p2), f2tff(p3));
        }
        Zs0 = Zs0 * corr0 + ls0;  Zs1 = Zs1 * corr1 + ls1;
        Zm0 = Zm0 * corr0 + lm0;  Zm1 = Zm1 * corr1 + lm1;
        __syncwarp();   // order P stores before P fragment loads (same warp)

        // --- rescale out accumulators ---
        #pragma unroll
        for (int dt = 0; dt < 8; dt++) {
            acc[dt][0] *= corr0; acc[dt][1] *= corr0;
            acc[dt][2] *= corr1; acc[dt][3] *= corr1;
        }

        // --- out += P[16q,64k] @ V[64k,64d] ---
        const uint32_t* Pu = (const uint32_t*)Pw;
        const uint32_t* Vu = (const uint32_t*)Vscur;
        #pragma unroll
        for (int ks = 0; ks < 8; ks++) {
            uint32_t a[4];
            a[0] = Pu[g * AT_STRIDE + ks * 8 + t];
            a[1] = Pu[(g + 8) * AT_STRIDE + ks * 8 + t];
            a[2] = Pu[g * AT_STRIDE + ks * 8 + t + 4];
            a[3] = Pu[(g + 8) * AT_STRIDE + ks * 8 + t + 4];
            #pragma unroll
            for (int dt = 0; dt < 8; dt++) {
                uint32_t bf[2] = { Vu[(ks * 8 + t) * AT_STRIDE + dt * 8 + g],
                                   Vu[(ks * 8 + t + 4) * AT_STRIDE + dt * 8 + g] };
                mma8(acc[dt], a, bf);
            }
        }

        // --- stage prefetched K/V into the other buffer ---
        if (has_next) {
            float* Ksn = Ks + (cur ^ 1) * 64 * AT_STRIDE;
            float* Vsn = Vs + (cur ^ 1) * 64 * AT_STRIDE;
            #pragma unroll
            for (int itl = 0; itl < 4; itl++) {
                int r = ldr + itl * 16;
                *(float4*)&Ksn[r * AT_STRIDE + ldc] =
                    make_float4(f2tff(kreg[itl].x), f2tff(kreg[itl].y),
                                f2tff(kreg[itl].z), f2tff(kreg[itl].w));
                *(float4*)&Vsn[r * AT_STRIDE + ldc] =
                    make_float4(f2tff(vreg[itl].x), f2tff(vreg[itl].y),
                                f2tff(vreg[itl].z), f2tff(vreg[itl].w));
            }
        }
        __syncthreads();
    }

    // final: reduce Z over quad lanes, normalize, store
    Zs0 += __shfl_xor_sync(0xffffffffu, Zs0, 1);
    Zs0 += __shfl_xor_sync(0xffffffffu, Zs0, 2);
    Zs1 += __shfl_xor_sync(0xffffffffu, Zs1, 1);
    Zs1 += __shfl_xor_sync(0xffffffffu, Zs1, 2);
    Zm0 += __shfl_xor_sync(0xffffffffu, Zm0, 1);
    Zm0 += __shfl_xor_sync(0xffffffffu, Zm0, 2);
    Zm1 += __shfl_xor_sync(0xffffffffu, Zm1, 1);
    Zm1 += __shfl_xor_sync(0xffffffffu, Zm1, 2);
    float inv0 = 1.0f / (Zm0 + 1e-8f * Zs0);
    float inv1 = 1.0f / (Zm1 + 1e-8f * Zs1);

    #pragma unroll
    for (int dt = 0; dt < 8; dt++) {
        int c = dt * 8 + 2 * t;
        *(float2*)&Obase[(size_t)(qw + g) * D_ + c] =
            make_float2(acc[dt][0] * inv0, acc[dt][1] * inv0);
        *(float2*)&Obase[(size_t)(qw + g + 8) * D_ + c] =
            make_float2(acc[dt][2] * inv1, acc[dt][3] * inv1);
    }
}

// ---------------------------------------------------------------------------
extern "C" void kernel_launch(void* const* d_in, const int* in_sizes, int n_in,
                              void* d_out, int out_size)
{
    const float* gene    = (const float*)d_in[0];
    const float* expr    = (const float*)d_in[1];
    const float* Mm      = (const float*)d_in[2];
    const float* W_fused = (const float*)d_in[3];
    const float* b_fused = (const float*)d_in[4];
    const float* W_Q     = (const float*)d_in[5];
    const float* b_Q     = (const float*)d_in[6];
    const float* W_K     = (const float*)d_in[7];
    const float* b_K     = (const float*)d_in[8];
    const float* W_V     = (const float*)d_in[9];
    const float* b_V     = (const float*)d_in[10];
    const float* W_O     = (const float*)d_in[11];
    const float* b_O     = (const float*)d_in[12];
    float* out = (float*)d_out;

    float *fusedp, *Qp, *Kp, *Vp, *attp;
    cudaGetSymbolAddress((void**)&fusedp, g_fused);
    cudaGetSymbolAddress((void**)&Qp, g_Q);
    cudaGetSymbolAddress((void**)&Kp, g_K);
    cudaGetSymbolAddress((void**)&Vp, g_V);
    cudaGetSymbolAddress((void**)&attp, g_att);

    cudaFuncSetAttribute(attn_tf32,
                         cudaFuncAttributeMaxDynamicSharedMemorySize, ATTN_SMEM);

    dim3 gg(D_ / 128, NR / 128);   // (4, 64)

    gemm_tf32<<<gg, 256>>>(gene, expr, 512, W_fused, b_fused, fusedp, 1024);
    gemm_tf32<<<gg, 256>>>(fusedp, fusedp, 512, W_Q, b_Q, Qp, 512);
    gemm_tf32<<<gg, 256>>>(fusedp, fusedp, 512, W_K, b_K, Kp, 512);
    gemm_tf32<<<gg, 256>>>(expr,   expr,   512, W_V, b_V, Vp, 512);
    attn_tf32<<<dim3(S_ / 128, H_, B_), 256, ATTN_SMEM>>>(Qp, Kp, Vp, Mm, attp);
    gemm_tf32<<<gg, 256>>>(attp, attp, 512, W_O, b_O, out, 512);
}

// round 8
// speedup vs baseline: 1.0948x; 1.0948x over previous
#include <cuda_runtime.h>
#include <math.h>
#include <stdint.h>

#define B_  4
#define S_  2048
#define D_  512
#define H_  8
#define HD_ 64
#define NR  (B_ * S_)   // 8192 rows

// Scratch buffers (no allocation allowed in kernel_launch).
__device__ __align__(16) float g_fused[NR * D_];
__device__ __align__(16) float g_Q[NR * D_];
__device__ __align__(16) float g_K[NR * D_];
__device__ __align__(16) float g_V[NR * D_];
__device__ __align__(16) float g_att[NR * D_];

// ---------------------------------------------------------------------------
// TF32 / cp.async helpers
// ---------------------------------------------------------------------------
__device__ __forceinline__ uint32_t f2tf(float x) {
    uint32_t u;
    asm("cvt.rna.tf32.f32 %0, %1;" : "=r"(u) : "f"(x));
    return u;
}
__device__ __forceinline__ float f2tff(float x) {
    return __uint_as_float(f2tf(x));
}
// D(16x8,f32) += A(16x8,tf32,row) * B(8x8,tf32,col)
__device__ __forceinline__ void mma8(float* d, const uint32_t* a, const uint32_t* b) {
    asm volatile(
        "mma.sync.aligned.m16n8k8.row.col.f32.tf32.tf32.f32 "
        "{%0,%1,%2,%3}, {%4,%5,%6,%7}, {%8,%9}, {%0,%1,%2,%3};"
        : "+f"(d[0]), "+f"(d[1]), "+f"(d[2]), "+f"(d[3])
        : "r"(a[0]), "r"(a[1]), "r"(a[2]), "r"(a[3]), "r"(b[0]), "r"(b[1]));
}
__device__ __forceinline__ void cp16(void* smem_dst, const void* gsrc) {
    uint32_t s = (uint32_t)__cvta_generic_to_shared(smem_dst);
    asm volatile("cp.async.cg.shared.global [%0], [%1], 16;" :: "r"(s), "l"(gsrc));
}
#define CP_COMMIT() asm volatile("cp.async.commit_group;")
#define CP_WAIT(n)  asm volatile("cp.async.wait_group %0;" :: "n"(n))

// ---------------------------------------------------------------------------
// TF32 tensor-core GEMM: C[M,512] = A[M,K] @ Bw[K,512] + bias.
// Double-buffered smem: one __syncthreads per k-iter, LDG prefetch overlaps mma.
// round_out=1: store outputs pre-rounded to tf32 (cvt.rna). Consumers that
// would re-apply cvt.rna on load see bit-identical values (idempotent).
// CTA 128x128, 256 threads, 8 warps (2m x 4n), warp tile 64x32.
// ---------------------------------------------------------------------------
__global__ __launch_bounds__(256, 2) void gemm_tf32(
    const float* __restrict__ A, const float* __restrict__ A2, int KA,
    const float* __restrict__ Bw, const float* __restrict__ bias,
    float* __restrict__ C, int K, int round_out)
{
    __shared__ float As[2][128][20];   // [m][k], pad: frag LDS conflict-free
    __shared__ float Bs[2][16][132];   // [k][n]

    const int tid  = threadIdx.x;
    const int lane = tid & 31, wid = tid >> 5;
    const int g = lane >> 2, t = lane & 3;
    const int wm = (wid >> 2) * 64;
    const int wn = (wid & 3) * 32;
    const int row0 = blockIdx.y * 128;
    const int col0 = blockIdx.x * 128;

    const int ar = tid >> 1;            // 0..127
    const int ac = (tid & 1) * 8;       // 0 or 8
    const int bk = tid >> 4;            // 0..15
    const int bc = (tid & 15) * 8;      // 0..120

    float acc[4][4][4];
    #pragma unroll
    for (int i = 0; i < 4; i++)
        #pragma unroll
        for (int j = 0; j < 4; j++)
            #pragma unroll
            for (int v = 0; v < 4; v++) acc[i][j][v] = 0.0f;

    const int niter = K >> 4;
    float4 pa0, pa1, pb0, pb1;

    auto prefetch = [&](int it) {
        int k0 = it << 4;
        const float* src = (k0 < KA) ? A : A2;
        int koff = (k0 < KA) ? k0 : k0 - KA;
        const float* p = &src[(size_t)(row0 + ar) * KA + koff + ac];
        pa0 = *(const float4*)p; pa1 = *(const float4*)(p + 4);
        const float* q = &Bw[(size_t)(k0 + bk) * D_ + col0 + bc];
        pb0 = *(const float4*)q; pb1 = *(const float4*)(q + 4);
    };
    auto stage = [&](int buf) {
        *(float4*)&As[buf][ar][ac]     = make_float4(f2tff(pa0.x), f2tff(pa0.y), f2tff(pa0.z), f2tff(pa0.w));
        *(float4*)&As[buf][ar][ac + 4] = make_float4(f2tff(pa1.x), f2tff(pa1.y), f2tff(pa1.z), f2tff(pa1.w));
        *(float4*)&Bs[buf][bk][bc]     = make_float4(f2tff(pb0.x), f2tff(pb0.y), f2tff(pb0.z), f2tff(pb0.w));
        *(float4*)&Bs[buf][bk][bc + 4] = make_float4(f2tff(pb1.x), f2tff(pb1.y), f2tff(pb1.z), f2tff(pb1.w));
    };

    prefetch(0);
    stage(0);
    __syncthreads();

    for (int it = 0; it < niter; it++) {
        const int cur = it & 1;
        if (it + 1 < niter) prefetch(it + 1);

        const uint32_t* Au = (const uint32_t*)As[cur];
        const uint32_t* Bu = (const uint32_t*)Bs[cur];
        #pragma unroll
        for (int ks = 0; ks < 2; ks++) {
            const int kk = ks * 8;
            uint32_t a[4][4];
            #pragma unroll
            for (int mt = 0; mt < 4; mt++) {
                int m = wm + mt * 16;
                a[mt][0] = Au[(m + g) * 20 + kk + t];
                a[mt][1] = Au[(m + g + 8) * 20 + kk + t];
                a[mt][2] = Au[(m + g) * 20 + kk + t + 4];
                a[mt][3] = Au[(m + g + 8) * 20 + kk + t + 4];
            }
            #pragma unroll
            for (int nt = 0; nt < 4; nt++) {
                int n = wn + nt * 8 + g;
                uint32_t bf[2] = { Bu[(kk + t) * 132 + n], Bu[(kk + t + 4) * 132 + n] };
                #pragma unroll
                for (int mt = 0; mt < 4; mt++) mma8(acc[mt][nt], a[mt], bf);
            }
        }

        if (it + 1 < niter) {
            stage(cur ^ 1);
            __syncthreads();
        }
    }

    // epilogue: bias + store (c0,c1 adjacent cols -> float2)
    #pragma unroll
    for (int mt = 0; mt < 4; mt++) {
        int r = row0 + wm + mt * 16 + g;
        #pragma unroll
        for (int nt = 0; nt < 4; nt++) {
            int c = col0 + wn + nt * 8 + 2 * t;
            float b0v = bias[c], b1v = bias[c + 1];
            float o0 = acc[mt][nt][0] + b0v, o1 = acc[mt][nt][1] + b1v;
            float o2 = acc[mt][nt][2] + b0v, o3 = acc[mt][nt][3] + b1v;
            if (round_out) {
                o0 = f2tff(o0); o1 = f2tff(o1); o2 = f2tff(o2); o3 = f2tff(o3);
            }
            *(float2*)&C[(size_t)r * D_ + c]       = make_float2(o0, o1);
            *(float2*)&C[(size_t)(r + 8) * D_ + c] = make_float2(o2, o3);
        }
    }
}

// ---------------------------------------------------------------------------
// TF32 fused masked-softmax attention (flash-style).
//   sL[q,k] = (scale*log2e) * M[q,k] * (Q[q]·K[k])
//   p = exp2(sL - mL);  Zs = sum p;  pm = p*M;  Zm = sum pm
//   out[q] = (sum_k pm * V[k]) / (Zm + EPS*Zs)
// CTA: 128 q rows, 256 threads (8 warps x 16q). 32 key blocks of 64.
// Q/K/V arrive PRE-ROUNDED to tf32 (producer GEMM round_out=1), so all tile
// movement is raw cp.async gmem->smem: zero staging registers, bit-identical
// numerics vs converting on load. Q fragments live in registers; P scratch
// aliases the dead Q smem region (warp-private rows). K/V double-buffered:
// next tile's cp.async issues after this iter's sync (buf^1 provably idle),
// overlapping the softmax+PV phases. One __syncthreads per iteration.
// M is read directly from gmem (L2-resident) in the C-fragment pattern.
// ---------------------------------------------------------------------------
#define AT_STRIDE 68
#define ATTN_SMEM ((128 * AT_STRIDE + 4 * 64 * AT_STRIDE) * 4)   // 104448 B

__global__ __launch_bounds__(256, 2) void attn_tf32(
    const float* __restrict__ Qg, const float* __restrict__ Kg,
    const float* __restrict__ Vg, const float* __restrict__ Mg,
    float* __restrict__ Og)
{
    extern __shared__ float sm[];
    float* Qs = sm;                            // [128][68] (q x d) -> later P scratch
    float* Ks = sm + 128 * AT_STRIDE;          // [2][64][68] (k x d)
    float* Vs = Ks + 2 * 64 * AT_STRIDE;       // [2][64][68] (k x d)
    float* Ps = sm;                            // aliases Qs (per-warp 16 rows)

    const int tid  = threadIdx.x;
    const int lane = tid & 31, w = tid >> 5;
    const int g = lane >> 2, t = lane & 3;
    const int qw = w * 16;
    const int b = blockIdx.z, h = blockIdx.y, qb = blockIdx.x;

    const float CL = 0.125f * 1.4426950408889634f;   // scale * log2e

    const float* Qbase = Qg + ((size_t)(b * S_ + qb * 128)) * D_ + h * HD_;
    const float* Kbase = Kg + ((size_t)(b * S_)) * D_ + h * HD_;
    const float* Vbase = Vg + ((size_t)(b * S_)) * D_ + h * HD_;
    const float* Mrow0 = Mg + (size_t)b * S_ * S_ + (size_t)(qb * 128 + qw + g) * S_;
    const float* Mrow1 = Mrow0 + (size_t)8 * S_;
    float*       Obase = Og + ((size_t)(b * S_ + qb * 128)) * D_ + h * HD_;

    const int ldr = tid >> 4;              // cooperative-load row base (0..15)
    const int ldc = (tid & 15) * 4;        // cooperative-load col

    // ---- prologue: cp.async Q (group A), then K/V tile 0 (group B) ----
    #pragma unroll
    for (int itl = 0; itl < 8; itl++) {
        int r = ldr + itl * 16;
        cp16(&Qs[r * AT_STRIDE + ldc], &Qbase[(size_t)r * D_ + ldc]);
    }
    CP_COMMIT();
    #pragma unroll
    for (int itl = 0; itl < 4; itl++) {
        int r = ldr + itl * 16;
        cp16(&Ks[r * AT_STRIDE + ldc], &Kbase[(size_t)r * D_ + ldc]);
        cp16(&Vs[r * AT_STRIDE + ldc], &Vbase[(size_t)r * D_ + ldc]);
    }
    CP_COMMIT();

    CP_WAIT(1);          // Q arrived (K/V tile 0 may still be in flight)
    __syncthreads();

    // ---- Q fragments -> registers (loop-invariant) ----
    uint32_t qa[8][4];
    {
        const uint32_t* Qu = (const uint32_t*)Qs;
        #pragma unroll
        for (int ks = 0; ks < 8; ks++) {
            qa[ks][0] = Qu[(qw + g) * AT_STRIDE + ks * 8 + t];
            qa[ks][1] = Qu[(qw + g + 8) * AT_STRIDE + ks * 8 + t];
            qa[ks][2] = Qu[(qw + g) * AT_STRIDE + ks * 8 + t + 4];
            qa[ks][3] = Qu[(qw + g + 8) * AT_STRIDE + ks * 8 + t + 4];
        }
    }

    float acc[8][4];
    #pragma unroll
    for (int i = 0; i < 8; i++)
        #pragma unroll
        for (int v = 0; v < 4; v++) acc[i][v] = 0.0f;
    float mL0 = -1e30f, mL1 = -1e30f;
    float Zs0 = 0.f, Zs1 = 0.f, Zm0 = 0.f, Zm1 = 0.f;

    for (int kb = 0; kb < S_ / 64; kb++) {
        const int cur = kb & 1;
        const bool has_next = (kb + 1 < S_ / 64);
        const float* Kscur = Ks + cur * 64 * AT_STRIDE;
        const float* Vscur = Vs + cur * 64 * AT_STRIDE;

        CP_WAIT(0);        // tile kb fully arrived
        __syncthreads();   // all warps see it; buf^1 reads from iter kb-1 done

        // --- scores: S[16q,64k] = Q @ K^T (warp) ---
        const uint32_t* Ku = (const uint32_t*)Kscur;
        float sc[8][4];
        #pragma unroll
        for (int nt = 0; nt < 8; nt++)
            #pragma unroll
            for (int v = 0; v < 4; v++) sc[nt][v] = 0.0f;

        #pragma unroll
        for (int ks = 0; ks < 8; ks++) {
            #pragma unroll
            for (int nt = 0; nt < 8; nt++) {
                uint32_t bf[2] = { Ku[(nt * 8 + g) * AT_STRIDE + ks * 8 + t],
                                   Ku[(nt * 8 + g) * AT_STRIDE + ks * 8 + t + 4] };
                mma8(sc[nt], qa[ks], bf);
            }
        }

        // --- issue cp.async for tile kb+1 into the other buffer ---
        // Safe: every thread passed this iter's __syncthreads, so no thread
        // still reads buf^1 (last read at iter kb-1). Copy overlaps softmax+PV.
        if (has_next) {
            float* Ksn = Ks + (cur ^ 1) * 64 * AT_STRIDE;
            float* Vsn = Vs + (cur ^ 1) * 64 * AT_STRIDE;
            #pragma unroll
            for (int itl = 0; itl < 4; itl++) {
                int r = ldr + itl * 16;
                cp16(&Ksn[r * AT_STRIDE + ldc],
                     &Kbase[(size_t)((kb + 1) * 64 + r) * D_ + ldc]);
                cp16(&Vsn[r * AT_STRIDE + ldc],
                     &Vbase[(size_t)((kb + 1) * 64 + r) * D_ + ldc]);
            }
            CP_COMMIT();
        }

        // --- mask * scale (log2 domain) from gmem, row max ---
        const float* Mc0 = Mrow0 + kb * 64;
        const float* Mc1 = Mrow1 + kb * 64;
        float mx0 = -1e30f, mx1 = -1e30f;
        #pragma unroll
        for (int nt = 0; nt < 8; nt++) {
            float2 mA = *(const float2*)&Mc0[nt * 8 + 2 * t];
            float2 mB = *(const float2*)&Mc1[nt * 8 + 2 * t];
            sc[nt][0] *= CL * mA.x;
            sc[nt][1] *= CL * mA.y;
            sc[nt][2] *= CL * mB.x;
            sc[nt][3] *= CL * mB.y;
            mx0 = fmaxf(mx0, fmaxf(sc[nt][0], sc[nt][1]));
            mx1 = fmaxf(mx1, fmaxf(sc[nt][2], sc[nt][3]));
        }
        mx0 = fmaxf(mx0, __shfl_xor_sync(0xffffffffu, mx0, 1));
        mx0 = fmaxf(mx0, __shfl_xor_sync(0xffffffffu, mx0, 2));
        mx1 = fmaxf(mx1, __shfl_xor_sync(0xffffffffu, mx1, 1));
        mx1 = fmaxf(mx1, __shfl_xor_sync(0xffffffffu, mx1, 2));

        float nm0 = fmaxf(mL0, mx0), nm1 = fmaxf(mL1, mx1);
        float corr0 = exp2f(mL0 - nm0), corr1 = exp2f(mL1 - nm1);
        mL0 = nm0; mL1 = nm1;

        // --- exp, Z accumulation, P (= p*M) to warp-private smem as tf32 ---
        float ls0 = 0.f, ls1 = 0.f, lm0 = 0.f, lm1 = 0.f;
        float* Pw = Ps + w * 16 * AT_STRIDE;
        #pragma unroll
        for (int nt = 0; nt < 8; nt++) {
            float2 mA = *(const float2*)&Mc0[nt * 8 + 2 * t];   // L1 hit
            float2 mB = *(const float2*)&Mc1[nt * 8 + 2 * t];
            float p0 = exp2f(sc[nt][0] - mL0);
            float p1 = exp2f(sc[nt][1] - mL0);
            float p2 = exp2f(sc[nt][2] - mL1);
            float p3 = exp2f(sc[nt][3] - mL1);
            ls0 += p0 + p1; ls1 += p2 + p3;
            p0 *= mA.x; p1 *= mA.y; p2 *= mB.x; p3 *= mB.y;
            lm0 += p0 + p1; lm1 += p2 + p3;
            *(float2*)&Pw[g * AT_STRIDE + nt * 8 + 2 * t] =
                make_float2(f2tff(p0), f2tff(p1));
            *(float2*)&Pw[(g + 8) * AT_STRIDE + nt * 8 + 2 * t] =
                make_float2(f2tff(p2), f2tff(p3));
        }
        Zs0 = Zs0 * corr0 + ls0;  Zs1 = Zs1 * corr1 + ls1;
        Zm0 = Zm0 * corr0 + lm0;  Zm1 = Zm1 * corr1 + lm1;
        __syncwarp();   // order P stores before P fragment loads (same warp)

        // --- rescale out accumulators ---
        #pragma unroll
        for (int dt = 0; dt < 8; dt++) {
            acc[dt][0] *= corr0; acc[dt][1] *= corr0;
            acc[dt][2] *= corr1; acc[dt][3] *= corr1;
        }

        // --- out += P[16q,64k] @ V[64k,64d] ---
        const uint32_t* Pu = (const uint32_t*)Pw;
        const uint32_t* Vu = (const uint32_t*)Vscur;
        #pragma unroll
        for (int ks = 0; ks < 8; ks++) {
            uint32_t a[4];
            a[0] = Pu[g * AT_STRIDE + ks * 8 + t];
            a[1] = Pu[(g + 8) * AT_STRIDE + ks * 8 + t];
            a[2] = Pu[g * AT_STRIDE + ks * 8 + t + 4];
            a[3] = Pu[(g + 8) * AT_STRIDE + ks * 8 + t + 4];
            #pragma unroll
            for (int dt = 0; dt < 8; dt++) {
                uint32_t bf[2] = { Vu[(ks * 8 + t) * AT_STRIDE + dt * 8 + g],
                                   Vu[(ks * 8 + t + 4) * AT_STRIDE + dt * 8 + g] };
                mma8(acc[dt], a, bf);
            }
        }
    }

    // final: reduce Z over quad lanes, normalize, store
    Zs0 += __shfl_xor_sync(0xffffffffu, Zs0, 1);
    Zs0 += __shfl_xor_sync(0xffffffffu, Zs0, 2);
    Zs1 += __shfl_xor_sync(0xffffffffu, Zs1, 1);
    Zs1 += __shfl_xor_sync(0xffffffffu, Zs1, 2);
    Zm0 += __shfl_xor_sync(0xffffffffu, Zm0, 1);
    Zm0 += __shfl_xor_sync(0xffffffffu, Zm0, 2);
    Zm1 += __shfl_xor_sync(0xffffffffu, Zm1, 1);
    Zm1 += __shfl_xor_sync(0xffffffffu, Zm1, 2);
    float inv0 = 1.0f / (Zm0 + 1e-8f * Zs0);
    float inv1 = 1.0f / (Zm1 + 1e-8f * Zs1);

    #pragma unroll
    for (int dt = 0; dt < 8; dt++) {
        int c = dt * 8 + 2 * t;
        *(float2*)&Obase[(size_t)(qw + g) * D_ + c] =
            make_float2(acc[dt][0] * inv0, acc[dt][1] * inv0);
        *(float2*)&Obase[(size_t)(qw + g + 8) * D_ + c] =
            make_float2(acc[dt][2] * inv1, acc[dt][3] * inv1);
    }
}

// ---------------------------------------------------------------------------
extern "C" void kernel_launch(void* const* d_in, const int* in_sizes, int n_in,
                              void* d_out, int out_size)
{
    const float* gene    = (const float*)d_in[0];
    const float* expr    = (const float*)d_in[1];
    const float* Mm      = (const float*)d_in[2];
    const float* W_fused = (const float*)d_in[3];
    const float* b_fused = (const float*)d_in[4];
    const float* W_Q     = (const float*)d_in[5];
    const float* b_Q     = (const float*)d_in[6];
    const float* W_K     = (const float*)d_in[7];
    const float* b_K     = (const float*)d_in[8];
    const float* W_V     = (const float*)d_in[9];
    const float* b_V     = (const float*)d_in[10];
    const float* W_O     = (const float*)d_in[11];
    const float* b_O     = (const float*)d_in[12];
    float* out = (float*)d_out;

    float *fusedp, *Qp, *Kp, *Vp, *attp;
    cudaGetSymbolAddress((void**)&fusedp, g_fused);
    cudaGetSymbolAddress((void**)&Qp, g_Q);
    cudaGetSymbolAddress((void**)&Kp, g_K);
    cudaGetSymbolAddress((void**)&Vp, g_V);
    cudaGetSymbolAddress((void**)&attp, g_att);

    cudaFuncSetAttribute(attn_tf32,
                         cudaFuncAttributeMaxDynamicSharedMemorySize, ATTN_SMEM);

    dim3 gg(D_ / 128, NR / 128);   // (4, 64)

    gemm_tf32<<<gg, 256>>>(gene, expr, 512, W_fused, b_fused, fusedp, 1024, 0);
    gemm_tf32<<<gg, 256>>>(fusedp, fusedp, 512, W_Q, b_Q, Qp, 512, 1);
    gemm_tf32<<<gg, 256>>>(fusedp, fusedp, 512, W_K, b_K, Kp, 512, 1);
    gemm_tf32<<<gg, 256>>>(expr,   expr,   512, W_V, b_V, Vp, 512, 1);
    attn_tf32<<<dim3(S_ / 128, H_, B_), 256, ATTN_SMEM>>>(Qp, Kp, Vp, Mm, attp);
    gemm_tf32<<<gg, 256>>>(attp, attp, 512, W_O, b_O, out, 512, 0);
}